// round 2
// baseline (speedup 1.0000x reference)
#include <cuda_runtime.h>
#include <cuda_bf16.h>

// Problem constants
#define BB 4
#define TT 2048
#define DD 1024
#define HH 16
#define HD 64
#define LAT 128
#define ROPE 32          // also = HD-ROPE (v dim)
#define NROW (BB*TT)     // 8192

// ---------------- scratch (static device arrays; no allocation allowed) ----
__device__ float g_qfull[NROW * DD];         // 32 MB : x @ Wq
__device__ float g_kv   [NROW * LAT];        //  4 MB : x @ Wkv
__device__ float g_khat [NROW * (HH*ROPE)];  // 16 MB : kv @ Wk
__device__ float g_vhat [NROW * (HH*ROPE)];  // 16 MB : kv @ Wv
__device__ float g_qr   [BB*HH*TT*ROPE];     // 16 MB : normalized q, [b,h,t,32]
__device__ float g_kr   [BB*HH*TT*ROPE];     // 16 MB : normalized k, [b,h,t,32]
__device__ float g_v    [BB*HH*TT*ROPE];     // 16 MB : v,            [b,h,t,32]
__device__ float g_attn [NROW * (HH*ROPE)];  // 16 MB : attn out, [b*T+t, h*32+d]

// ---------------- tiled SGEMM: C[M,N] = A[M,K] @ B[K,N] ---------------------
// 64x64 tile, BK=16, 256 threads, 4x4 per thread.
// MAPB: remap B's row index r -> (r>>5)*64 + (r&31)   (skip zero-padded Wo rows)
template <bool MAPB>
__global__ void __launch_bounds__(256) sgemm64(const float* __restrict__ A,
                                               const float* __restrict__ B,
                                               float* __restrict__ C,
                                               int M, int N, int K) {
    __shared__ float As[16][64];
    __shared__ float Bs[16][64];

    const int n0 = blockIdx.x * 64;
    const int m0 = blockIdx.y * 64;
    const int tid = threadIdx.x;
    const int tx = tid & 15, ty = tid >> 4;

    // load indices
    const int am = tid >> 2;             // 0..63
    const int ak = (tid & 3) << 2;       // 0,4,8,12
    const int bk = tid >> 4;             // 0..15
    const int bn = (tid & 15) << 2;      // 0..60

    float acc[4][4];
#pragma unroll
    for (int i = 0; i < 4; i++)
#pragma unroll
        for (int j = 0; j < 4; j++) acc[i][j] = 0.f;

    for (int k0 = 0; k0 < K; k0 += 16) {
        float4 av = *(const float4*)&A[(size_t)(m0 + am) * K + k0 + ak];
        As[ak + 0][am] = av.x;
        As[ak + 1][am] = av.y;
        As[ak + 2][am] = av.z;
        As[ak + 3][am] = av.w;

        int brow = k0 + bk;
        if (MAPB) brow = ((brow >> 5) << 6) | (brow & 31);
        *(float4*)&Bs[bk][bn] = *(const float4*)&B[(size_t)brow * N + n0 + bn];

        __syncthreads();
#pragma unroll
        for (int kk = 0; kk < 16; kk++) {
            float4 a = *(float4*)&As[kk][ty << 2];
            float4 b = *(float4*)&Bs[kk][tx << 2];
            acc[0][0] += a.x * b.x; acc[0][1] += a.x * b.y; acc[0][2] += a.x * b.z; acc[0][3] += a.x * b.w;
            acc[1][0] += a.y * b.x; acc[1][1] += a.y * b.y; acc[1][2] += a.y * b.z; acc[1][3] += a.y * b.w;
            acc[2][0] += a.z * b.x; acc[2][1] += a.z * b.y; acc[2][2] += a.z * b.z; acc[2][3] += a.z * b.w;
            acc[3][0] += a.w * b.x; acc[3][1] += a.w * b.y; acc[3][2] += a.w * b.z; acc[3][3] += a.w * b.w;
        }
        __syncthreads();
    }

#pragma unroll
    for (int i = 0; i < 4; i++) {
        float4 v = make_float4(acc[i][0], acc[i][1], acc[i][2], acc[i][3]);
        *(float4*)&C[(size_t)(m0 + (ty << 2) + i) * N + n0 + (tx << 2)] = v;
    }
}

// ---------------- q RMSNorm: one warp per (row, head) -----------------------
// qfull [8192,1024]; out [b,h,t,32] keeping first ROPE dims, scale folded later.
__global__ void qnorm_kernel(const float* __restrict__ qfull,
                             const float* __restrict__ q_g,
                             float* __restrict__ qr) {
    int gw = (blockIdx.x * blockDim.x + threadIdx.x) >> 5;  // warp id
    int lane = threadIdx.x & 31;
    int row = gw >> 4;        // b*T+t
    int h = gw & 15;
    const float* p = qfull + (size_t)row * DD + h * HD;
    float v0 = p[lane];
    float v1 = p[lane + 32];
    float ss = v0 * v0 + v1 * v1;
#pragma unroll
    for (int o = 16; o; o >>= 1) ss += __shfl_xor_sync(0xffffffffu, ss, o);
    float r = rsqrtf(ss * (1.f / HD) + 1e-6f);
    int b = row >> 11, t = row & (TT - 1);
    qr[(((size_t)(b * HH + h) * TT + t) << 5) + lane] = v0 * r * q_g[lane];
}

// ---------------- k RMSNorm + v permute: one warp per (row, head) -----------
__global__ void kvpack_kernel(const float* __restrict__ khat,
                              const float* __restrict__ vhat,
                              const float* __restrict__ k_g,
                              float* __restrict__ kr,
                              float* __restrict__ vv) {
    int gw = (blockIdx.x * blockDim.x + threadIdx.x) >> 5;
    int lane = threadIdx.x & 31;
    int row = gw >> 4;
    int h = gw & 15;
    size_t src = (size_t)row * (HH * ROPE) + h * ROPE + lane;
    float kvl = khat[src];
    float ss = kvl * kvl;
#pragma unroll
    for (int o = 16; o; o >>= 1) ss += __shfl_xor_sync(0xffffffffu, ss, o);
    float r = rsqrtf(ss * (1.f / ROPE) + 1e-6f);
    int b = row >> 11, t = row & (TT - 1);
    size_t dst = (((size_t)(b * HH + h) * TT + t) << 5) + lane;
    kr[dst] = kvl * r * k_g[lane];
    vv[dst] = vhat[src];
}

// ---------------- flash attention: d=32, causal -----------------------------
// grid (T/64, B*H), block 64 threads; thread = one query row.
__global__ void __launch_bounds__(64) attn_kernel(const float* __restrict__ qr,
                                                  const float* __restrict__ kr,
                                                  const float* __restrict__ vv,
                                                  float* __restrict__ out) {
    const int bh = blockIdx.y;              // 0..63
    const int m0 = blockIdx.x * 64;
    const int tid = threadIdx.x;            // 0..63
    const int qrow = m0 + tid;

    const float* qb = qr + (((size_t)bh * TT + qrow) << 5);
    float q[32];
#pragma unroll
    for (int d = 0; d < 32; d++) q[d] = qb[d] * 0.125f;  // 1/sqrt(64) folded in

    float o[32];
#pragma unroll
    for (int d = 0; d < 32; d++) o[d] = 0.f;
    float mi = -1e30f, li = 0.f;

    __shared__ float Ks[64][32];
    __shared__ float Vs[64][32];
    const float* kb = kr + ((size_t)bh * TT << 5);
    const float* vb = vv + ((size_t)bh * TT << 5);

    const int kend = m0 + 64;
    for (int n0 = 0; n0 < kend; n0 += 64) {
        __syncthreads();
        // 64x32 floats each -> 512 float4s per tile; 64 threads x 8 each
#pragma unroll
        for (int i = 0; i < 8; i++) {
            int idx = tid + i * 64;       // 0..511
            int r = idx >> 3, c = (idx & 7) << 2;
            *(float4*)&Ks[r][c] = *(const float4*)&kb[((n0 + r) << 5) + c];
            *(float4*)&Vs[r][c] = *(const float4*)&vb[((n0 + r) << 5) + c];
        }
        __syncthreads();

        for (int j = 0; j < 64; j++) {
            if (n0 + j > qrow) break;     // causal
            float s = 0.f;
#pragma unroll
            for (int d = 0; d < 32; d++) s += q[d] * Ks[j][d];
            if (s > mi) {
                float corr = __expf(mi - s);
                li = li * corr + 1.f;
#pragma unroll
                for (int d = 0; d < 32; d++) o[d] = o[d] * corr + Vs[j][d];
                mi = s;
            } else {
                float p = __expf(s - mi);
                li += p;
#pragma unroll
                for (int d = 0; d < 32; d++) o[d] += p * Vs[j][d];
            }
        }
    }

    float inv = 1.f / li;
    int b = bh >> 4, h = bh & 15;
    float* op = out + (size_t)(b * TT + qrow) * (HH * ROPE) + h * ROPE;
#pragma unroll
    for (int d = 0; d < 32; d++) op[d] = o[d] * inv;
}

// ---------------- launch -----------------------------------------------------
extern "C" void kernel_launch(void* const* d_in, const int* in_sizes, int n_in,
                              void* d_out, int out_size) {
    const float* x   = (const float*)d_in[0];
    const float* Wq  = (const float*)d_in[1];
    const float* Wkv = (const float*)d_in[2];
    const float* Wk  = (const float*)d_in[3];
    const float* Wv  = (const float*)d_in[4];
    const float* Wo  = (const float*)d_in[5];
    const float* q_g = (const float*)d_in[6];
    const float* k_g = (const float*)d_in[7];
    float* out = (float*)d_out;

    float *qfull, *kv, *khat, *vhat, *qr, *kr, *vv, *attn;
    cudaGetSymbolAddress((void**)&qfull, g_qfull);
    cudaGetSymbolAddress((void**)&kv,    g_kv);
    cudaGetSymbolAddress((void**)&khat,  g_khat);
    cudaGetSymbolAddress((void**)&vhat,  g_vhat);
    cudaGetSymbolAddress((void**)&qr,    g_qr);
    cudaGetSymbolAddress((void**)&kr,    g_kr);
    cudaGetSymbolAddress((void**)&vv,    g_v);
    cudaGetSymbolAddress((void**)&attn,  g_attn);

    // 1) q_full = x @ Wq         [8192,1024]
    sgemm64<false><<<dim3(DD / 64, NROW / 64), 256>>>(x, Wq, qfull, NROW, DD, DD);
    // 2) kv = x @ Wkv            [8192,128]
    sgemm64<false><<<dim3(LAT / 64, NROW / 64), 256>>>(x, Wkv, kv, NROW, LAT, DD);
    // 3) khat = kv @ Wk          [8192,512]
    sgemm64<false><<<dim3((HH * ROPE) / 64, NROW / 64), 256>>>(kv, Wk, khat, NROW, HH * ROPE, LAT);
    // 4) vhat = kv @ Wv          [8192,512]
    sgemm64<false><<<dim3((HH * ROPE) / 64, NROW / 64), 256>>>(kv, Wv, vhat, NROW, HH * ROPE, LAT);
    // 5) q RMSNorm -> [b,h,t,32]
    qnorm_kernel<<<(NROW * HH) / 8, 256>>>(qfull, q_g, qr);
    // 6) k RMSNorm + v permute -> [b,h,t,32]
    kvpack_kernel<<<(NROW * HH) / 8, 256>>>(khat, vhat, k_g, kr, vv);
    // 7) causal flash attention -> attn [b*T+t, h*32+d]
    attn_kernel<<<dim3(TT / 64, BB * HH), 64>>>(qr, kr, vv, attn);
    // 8) out = attn @ Wo (zero-padded rows of Wo skipped via row map)
    sgemm64<true><<<dim3(DD / 64, NROW / 64), 256>>>(attn, Wo, out, NROW, DD, HH * ROPE);
}

// round 6
// speedup vs baseline: 1.4035x; 1.4035x over previous
#include <cuda_runtime.h>
#include <cuda_bf16.h>

// Problem constants
#define BB 4
#define TT 2048
#define DD 1024
#define HH 16
#define HD 64
#define LAT 128
#define ROPE 32          // also = HD-ROPE (v dim)
#define NROW (BB*TT)     // 8192

// ---------------- scratch (static device arrays; no allocation allowed) ----
__device__ float g_qfull[NROW * DD];         // 32 MB : x @ Wq
__device__ float g_kv   [NROW * LAT];        //  4 MB : x @ Wkv
__device__ float g_khat [NROW * (HH*ROPE)];  // 16 MB : kv @ Wk
__device__ float g_vhat [NROW * (HH*ROPE)];  // 16 MB : kv @ Wv
__device__ float g_qr   [BB*HH*TT*ROPE];     // 16 MB : normalized q, [b,h,t,32]
__device__ float g_kr   [BB*HH*TT*ROPE];     // 16 MB : normalized k, [b,h,t,32]
__device__ float g_v    [BB*HH*TT*ROPE];     // 16 MB : v,            [b,h,t,32]
__device__ float g_attn [NROW * (HH*ROPE)];  // 16 MB : attn out, [b*T+t, h*32+d]

// fp32 -> tf32 (round to nearest) ------------------------------------------
__device__ __forceinline__ float f2tf32(float x) {
    float y;
    asm("cvt.rna.tf32.f32 %0, %1;" : "=f"(y) : "f"(x));
    return y;
}

__device__ __forceinline__ void mma_tf32(float& c0, float& c1, float& c2, float& c3,
                                         unsigned a0, unsigned a1, unsigned a2, unsigned a3,
                                         unsigned b0, unsigned b1) {
    asm volatile(
        "mma.sync.aligned.m16n8k8.row.col.f32.tf32.tf32.f32 "
        "{%0,%1,%2,%3}, {%4,%5,%6,%7}, {%8,%9}, {%0,%1,%2,%3};"
        : "+f"(c0), "+f"(c1), "+f"(c2), "+f"(c3)
        : "r"(a0), "r"(a1), "r"(a2), "r"(a3), "r"(b0), "r"(b1));
}

// ---------------- TF32 tensor-core GEMM: C[M,N] = A[M,K] @ B[K,N] -----------
// CTA tile 128x64, BK=16, 256 threads (8 warps), warp tile 32x32.
// MAPB: remap B's row index r -> (r>>5)*64 + (r&31)  (skip zero-padded Wo rows)
template <bool MAPB>
__global__ void __launch_bounds__(256) gemm_tf32(const float* __restrict__ A,
                                                 const float* __restrict__ B,
                                                 float* __restrict__ C,
                                                 int M, int N, int K) {
    __shared__ float As[128][20];   // [m][k], pad 20 -> conflict-free frag loads
    __shared__ float Bs[16][72];    // [k][n], pad 72 -> conflict-free frag loads

    const int m0 = blockIdx.y * 128;
    const int n0 = blockIdx.x * 64;
    const int tid  = threadIdx.x;
    const int warp = tid >> 5;
    const int lane = tid & 31;
    const int wm = (warp & 3) << 5;   // 0,32,64,96
    const int wn = (warp >> 2) << 5;  // 0,32
    const int gid = lane >> 2;        // 0..7
    const int tig = lane & 3;         // 0..3

    // global load indices
    const int ar = tid >> 2;          // 0..63  (rows ar and ar+64)
    const int ac = (tid & 3) << 2;    // 0,4,8,12
    const int br = tid >> 4;          // 0..15
    const int bc = (tid & 15) << 2;   // 0..60

    float c[8][4];
#pragma unroll
    for (int i = 0; i < 8; i++)
#pragma unroll
        for (int j = 0; j < 4; j++) c[i][j] = 0.f;

    for (int k0 = 0; k0 < K; k0 += 16) {
        float4 av0 = *(const float4*)&A[(size_t)(m0 + ar) * K + k0 + ac];
        float4 av1 = *(const float4*)&A[(size_t)(m0 + ar + 64) * K + k0 + ac];
        int brow = k0 + br;
        if (MAPB) brow = ((brow >> 5) << 6) | (brow & 31);
        float4 bv = *(const float4*)&B[(size_t)brow * N + n0 + bc];

        __syncthreads();   // previous iteration's compute done
        As[ar][ac + 0] = f2tf32(av0.x);
        As[ar][ac + 1] = f2tf32(av0.y);
        As[ar][ac + 2] = f2tf32(av0.z);
        As[ar][ac + 3] = f2tf32(av0.w);
        As[ar + 64][ac + 0] = f2tf32(av1.x);
        As[ar + 64][ac + 1] = f2tf32(av1.y);
        As[ar + 64][ac + 2] = f2tf32(av1.z);
        As[ar + 64][ac + 3] = f2tf32(av1.w);
        Bs[br][bc + 0] = f2tf32(bv.x);
        Bs[br][bc + 1] = f2tf32(bv.y);
        Bs[br][bc + 2] = f2tf32(bv.z);
        Bs[br][bc + 3] = f2tf32(bv.w);
        __syncthreads();

#pragma unroll
        for (int kk = 0; kk < 16; kk += 8) {
            unsigned a[2][4], b[4][2];
#pragma unroll
            for (int mt = 0; mt < 2; mt++) {
                int r = wm + (mt << 4) + gid;
                a[mt][0] = __float_as_uint(As[r    ][kk + tig]);
                a[mt][1] = __float_as_uint(As[r + 8][kk + tig]);
                a[mt][2] = __float_as_uint(As[r    ][kk + tig + 4]);
                a[mt][3] = __float_as_uint(As[r + 8][kk + tig + 4]);
            }
#pragma unroll
            for (int nt = 0; nt < 4; nt++) {
                int cidx = wn + (nt << 3) + gid;
                b[nt][0] = __float_as_uint(Bs[kk + tig    ][cidx]);
                b[nt][1] = __float_as_uint(Bs[kk + tig + 4][cidx]);
            }
#pragma unroll
            for (int mt = 0; mt < 2; mt++)
#pragma unroll
                for (int nt = 0; nt < 4; nt++) {
                    int i = (mt << 2) + nt;
                    mma_tf32(c[i][0], c[i][1], c[i][2], c[i][3],
                             a[mt][0], a[mt][1], a[mt][2], a[mt][3],
                             b[nt][0], b[nt][1]);
                }
        }
    }

    // epilogue
#pragma unroll
    for (int mt = 0; mt < 2; mt++)
#pragma unroll
        for (int nt = 0; nt < 4; nt++) {
            int i = (mt << 2) + nt;
            int row = m0 + wm + (mt << 4) + gid;
            int col = n0 + wn + (nt << 3) + (tig << 1);
            *(float2*)&C[(size_t)row * N + col] = make_float2(c[i][0], c[i][1]);
            *(float2*)&C[(size_t)(row + 8) * N + col] = make_float2(c[i][2], c[i][3]);
        }
}

// ---------------- q RMSNorm: one warp per (row, head) -----------------------
__global__ void qnorm_kernel(const float* __restrict__ qfull,
                             const float* __restrict__ q_g,
                             float* __restrict__ qr) {
    int gw = (blockIdx.x * blockDim.x + threadIdx.x) >> 5;  // warp id
    int lane = threadIdx.x & 31;
    int row = gw >> 4;        // b*T+t
    int h = gw & 15;
    const float* p = qfull + (size_t)row * DD + h * HD;
    float v0 = p[lane];
    float v1 = p[lane + 32];
    float ss = v0 * v0 + v1 * v1;
#pragma unroll
    for (int o = 16; o; o >>= 1) ss += __shfl_xor_sync(0xffffffffu, ss, o);
    float r = rsqrtf(ss * (1.f / HD) + 1e-6f);
    int b = row >> 11, t = row & (TT - 1);
    qr[(((size_t)(b * HH + h) * TT + t) << 5) + lane] = v0 * r * q_g[lane];
}

// ---------------- k RMSNorm + v permute: one warp per (row, head) -----------
__global__ void kvpack_kernel(const float* __restrict__ khat,
                              const float* __restrict__ vhat,
                              const float* __restrict__ k_g,
                              float* __restrict__ kr,
                              float* __restrict__ vv) {
    int gw = (blockIdx.x * blockDim.x + threadIdx.x) >> 5;
    int lane = threadIdx.x & 31;
    int row = gw >> 4;
    int h = gw & 15;
    size_t src = (size_t)row * (HH * ROPE) + h * ROPE + lane;
    float kvl = khat[src];
    float ss = kvl * kvl;
#pragma unroll
    for (int o = 16; o; o >>= 1) ss += __shfl_xor_sync(0xffffffffu, ss, o);
    float r = rsqrtf(ss * (1.f / ROPE) + 1e-6f);
    int b = row >> 11, t = row & (TT - 1);
    size_t dst = (((size_t)(b * HH + h) * TT + t) << 5) + lane;
    kr[dst] = kvl * r * k_g[lane];
    vv[dst] = vhat[src];
}

// ---------------- flash attention: d=32, causal -----------------------------
// grid (T/64, B*H), block 64 threads; thread = one query row.
__global__ void __launch_bounds__(64) attn_kernel(const float* __restrict__ qr,
                                                  const float* __restrict__ kr,
                                                  const float* __restrict__ vv,
                                                  float* __restrict__ out) {
    const int bh = blockIdx.y;              // 0..63
    const int m0 = blockIdx.x * 64;
    const int tid = threadIdx.x;            // 0..63
    const int qrow = m0 + tid;

    const float* qb = qr + (((size_t)bh * TT + qrow) << 5);
    float q[32];
#pragma unroll
    for (int d = 0; d < 32; d++) q[d] = qb[d] * 0.125f;  // 1/sqrt(64) folded in

    float o[32];
#pragma unroll
    for (int d = 0; d < 32; d++) o[d] = 0.f;
    float mi = -1e30f, li = 0.f;

    __shared__ float Ks[64][32];
    __shared__ float Vs[64][32];
    const float* kb = kr + ((size_t)bh * TT << 5);
    const float* vb = vv + ((size_t)bh * TT << 5);

    const int kend = m0 + 64;
    for (int n0 = 0; n0 < kend; n0 += 64) {
        __syncthreads();
#pragma unroll
        for (int i = 0; i < 8; i++) {
            int idx = tid + i * 64;       // 0..511
            int r = idx >> 3, cc = (idx & 7) << 2;
            *(float4*)&Ks[r][cc] = *(const float4*)&kb[((n0 + r) << 5) + cc];
            *(float4*)&Vs[r][cc] = *(const float4*)&vb[((n0 + r) << 5) + cc];
        }
        __syncthreads();

        for (int j = 0; j < 64; j++) {
            if (n0 + j > qrow) break;     // causal
            float s = 0.f;
#pragma unroll
            for (int d = 0; d < 32; d++) s += q[d] * Ks[j][d];
            if (s > mi) {
                float corr = __expf(mi - s);
                li = li * corr + 1.f;
#pragma unroll
                for (int d = 0; d < 32; d++) o[d] = o[d] * corr + Vs[j][d];
                mi = s;
            } else {
                float p = __expf(s - mi);
                li += p;
#pragma unroll
                for (int d = 0; d < 32; d++) o[d] += p * Vs[j][d];
            }
        }
    }

    float inv = 1.f / li;
    int b = bh >> 4, h = bh & 15;
    float* op = out + (size_t)(b * TT + qrow) * (HH * ROPE) + h * ROPE;
#pragma unroll
    for (int d = 0; d < 32; d++) op[d] = o[d] * inv;
}

// ---------------- launch -----------------------------------------------------
extern "C" void kernel_launch(void* const* d_in, const int* in_sizes, int n_in,
                              void* d_out, int out_size) {
    const float* x   = (const float*)d_in[0];
    const float* Wq  = (const float*)d_in[1];
    const float* Wkv = (const float*)d_in[2];
    const float* Wk  = (const float*)d_in[3];
    const float* Wv  = (const float*)d_in[4];
    const float* Wo  = (const float*)d_in[5];
    const float* q_g = (const float*)d_in[6];
    const float* k_g = (const float*)d_in[7];
    float* out = (float*)d_out;

    float *qfull, *kv, *khat, *vhat, *qr, *kr, *vv, *attn;
    cudaGetSymbolAddress((void**)&qfull, g_qfull);
    cudaGetSymbolAddress((void**)&kv,    g_kv);
    cudaGetSymbolAddress((void**)&khat,  g_khat);
    cudaGetSymbolAddress((void**)&vhat,  g_vhat);
    cudaGetSymbolAddress((void**)&qr,    g_qr);
    cudaGetSymbolAddress((void**)&kr,    g_kr);
    cudaGetSymbolAddress((void**)&vv,    g_v);
    cudaGetSymbolAddress((void**)&attn,  g_attn);

    // 1) q_full = x @ Wq         [8192,1024]
    gemm_tf32<false><<<dim3(DD / 64, NROW / 128), 256>>>(x, Wq, qfull, NROW, DD, DD);
    // 2) kv = x @ Wkv            [8192,128]
    gemm_tf32<false><<<dim3(LAT / 64, NROW / 128), 256>>>(x, Wkv, kv, NROW, LAT, DD);
    // 3) khat = kv @ Wk          [8192,512]
    gemm_tf32<false><<<dim3((HH * ROPE) / 64, NROW / 128), 256>>>(kv, Wk, khat, NROW, HH * ROPE, LAT);
    // 4) vhat = kv @ Wv          [8192,512]
    gemm_tf32<false><<<dim3((HH * ROPE) / 64, NROW / 128), 256>>>(kv, Wv, vhat, NROW, HH * ROPE, LAT);
    // 5) q RMSNorm -> [b,h,t,32]
    qnorm_kernel<<<(NROW * HH) / 8, 256>>>(qfull, q_g, qr);
    // 6) k RMSNorm + v permute -> [b,h,t,32]
    kvpack_kernel<<<(NROW * HH) / 8, 256>>>(khat, vhat, k_g, kr, vv);
    // 7) causal flash attention -> attn [b*T+t, h*32+d]
    attn_kernel<<<dim3(TT / 64, BB * HH), 64>>>(qr, kr, vv, attn);
    // 8) out = attn @ Wo (zero-padded rows of Wo skipped via row map)
    gemm_tf32<true><<<dim3(DD / 64, NROW / 128), 256>>>(attn, Wo, out, NROW, DD, HH * ROPE);
}